// round 15
// baseline (speedup 1.0000x reference)
#include <cuda_runtime.h>
#include <math.h>
#include <stdint.h>

#define B_ 8
#define N_ 1024
#define C_ 768
#define H_ 12
#define D_ 64
#define BH_ (B_*H_)

// Scratch (device globals — no allocation allowed)
__device__ float    g_q [BH_*N_*D_];    // fp32 from GEMM; LN rewrites tf32 bits
__device__ float    g_k [BH_*N_*D_];    // fp32 from GEMM; LN rewrites tf32 bits
__device__ uint32_t g_vt[BH_*D_*N_];    // V^T tf32 bits: [bh][d][n]
__device__ uint32_t g_ao[B_*N_*C_];     // attention output, tf32 bits, [B,N,C]
__device__ uint32_t gx_tf [B_*N_*C_];   // x pre-converted to tf32 bits
__device__ uint32_t gw1_tf[3*C_*C_];    // wqkv pre-converted
__device__ uint32_t gw2_tf[C_*C_];      // wproj pre-converted

// ---------------------------------------------------------------------------
// helpers
// ---------------------------------------------------------------------------
__device__ __forceinline__ uint32_t f2tf(float f) {
    uint32_t u;
    asm("cvt.rna.tf32.f32 %0, %1;" : "=r"(u) : "f"(f));
    return u;
}

__device__ __forceinline__ float fexp2(float x) {
    float y;
    asm("ex2.approx.f32 %0, %1;" : "=f"(y) : "f"(x));
    return y;
}

__device__ __forceinline__ void mma8(float* c, const uint32_t* a, const uint32_t* b) {
    asm volatile(
        "mma.sync.aligned.m16n8k8.row.col.f32.tf32.tf32.f32 "
        "{%0,%1,%2,%3},{%4,%5,%6,%7},{%8,%9},{%0,%1,%2,%3};"
        : "+f"(c[0]), "+f"(c[1]), "+f"(c[2]), "+f"(c[3])
        : "r"(a[0]), "r"(a[1]), "r"(a[2]), "r"(a[3]), "r"(b[0]), "r"(b[1]));
}

__device__ __forceinline__ uint32_t smem_u32(const void* p) {
    uint32_t a;
    asm("{ .reg .u64 t; cvta.to.shared.u64 t, %1; cvt.u32.u64 %0, t; }"
        : "=r"(a) : "l"(p));
    return a;
}

__device__ __forceinline__ void ldsm4(uint32_t* r, uint32_t addr) {
    asm volatile("ldmatrix.sync.aligned.m8n8.x4.shared.b16 {%0,%1,%2,%3}, [%4];"
        : "=r"(r[0]), "=r"(r[1]), "=r"(r[2]), "=r"(r[3]) : "r"(addr));
}

__device__ __forceinline__ void cpasync16(uint32_t smem_addr, const void* gptr) {
    asm volatile("cp.async.cg.shared.global [%0], [%1], 16;"
        :: "r"(smem_addr), "l"(gptr) : "memory");
}
#define CP_COMMIT() asm volatile("cp.async.commit_group;" ::: "memory")

// ---------------------------------------------------------------------------
// Pre-convert pass: x, wqkv, wproj -> tf32 bit arrays
// ---------------------------------------------------------------------------
#define NXV ((B_*N_*C_)/4)
#define NW1V ((3*C_*C_)/4)
#define NW2V ((C_*C_)/4)
#define NTOTV (NXV + NW1V + NW2V)

__global__ __launch_bounds__(256)
void cvt_kernel(const float4* __restrict__ x, const float4* __restrict__ w1,
                const float4* __restrict__ w2)
{
    const int i = blockIdx.x * blockDim.x + threadIdx.x;
    if (i >= NTOTV) return;
    float4 v; uint4* dst;
    if (i < NXV)            { v = x[i];               dst = (uint4*)gx_tf  + i; }
    else if (i < NXV+NW1V)  { v = w1[i - NXV];        dst = (uint4*)gw1_tf + (i - NXV); }
    else                    { v = w2[i - NXV - NW1V]; dst = (uint4*)gw2_tf + (i - NXV - NW1V); }
    *dst = make_uint4(f2tf(v.x), f2tf(v.y), f2tf(v.z), f2tf(v.w));
}

// ---------------------------------------------------------------------------
// tf32 GEMM on pre-converted inputs (cp.async 2-STAGE pipeline -> 3 blocks/SM).
// MODE 0: q,k scattered fp32; v scattered TRANSPOSED tf32 bits into g_vt.
// MODE 1: row-major fp32 store to Y.
// ---------------------------------------------------------------------------
#define KPG 36
#define STG_W (128*KPG)

template<int MODE>
__global__ __launch_bounds__(256)
void gemm_tf32(const uint32_t* __restrict__ A, const uint32_t* __restrict__ W,
               float* __restrict__ Y)
{
    extern __shared__ uint32_t smem[];
    uint32_t* As = smem;              // 2*STG_W
    uint32_t* Ws = smem + 2*STG_W;    // 2*STG_W

    const int tid  = threadIdx.x;
    const int warp = tid >> 5, lane = tid & 31;
    const int g    = lane >> 2, tig = lane & 3;
    const int wm   = (warp >> 2) * 64;
    const int wn   = (warp & 3)  * 32;
    const int bm   = blockIdx.y * 128;
    const int bn   = blockIdx.x * 128;
    const int K    = C_;
    const int nk   = K / 32;          // 24

    const int lrow = tid >> 1;
    const int lhf  = (tid & 1) * 16;
    const uint32_t sA0 = smem_u32(As) + (uint32_t)((lrow*KPG + lhf) * 4);
    const uint32_t sW0 = smem_u32(Ws) + (uint32_t)((lrow*KPG + lhf) * 4);
    const uint32_t* gA = A + (size_t)(bm + lrow) * K + lhf;
    const uint32_t* gW = W + (size_t)(bn + lrow) * K + lhf;

    const uint32_t a_lane = smem_u32(As)
        + (uint32_t)((((wm + (lane & 15)) * KPG + ((lane >> 4) << 2))) * 4);
    const uint32_t b_lane = smem_u32(Ws)
        + (uint32_t)((((wn + (lane & 7) + ((lane >> 4) << 3)) * KPG
                      + (((lane >> 3) & 1) << 2))) * 4);

    float acc[4][4][4];
    #pragma unroll
    for (int i = 0; i < 4; i++)
        #pragma unroll
        for (int j = 0; j < 4; j++)
            #pragma unroll
            for (int e = 0; e < 4; e++) acc[i][j][e] = 0.f;

    auto issue = [&](int s) {
        const uint32_t so = (uint32_t)((s & 1) * STG_W * 4);
        const uint32_t* ga = gA + s*32;
        const uint32_t* gw = gW + s*32;
        #pragma unroll
        for (int q = 0; q < 4; q++) {
            cpasync16(sA0 + so + q*16, ga + q*4);
            cpasync16(sW0 + so + q*16, gw + q*4);
        }
        CP_COMMIT();
    };

    issue(0);
    if (nk > 1) issue(1);

    for (int i = 0; i < nk; i++) {
        if (i + 1 < nk) asm volatile("cp.async.wait_group 1;" ::: "memory");
        else            asm volatile("cp.async.wait_group 0;" ::: "memory");
        __syncthreads();    // stage i landed & visible

        const uint32_t ab = a_lane + (uint32_t)((i & 1) * STG_W * 4);
        const uint32_t bb = b_lane + (uint32_t)((i & 1) * STG_W * 4);
        #pragma unroll
        for (int kk = 0; kk < 4; kk++) {
            const uint32_t kko = kk * 32;
            uint32_t af[4][4];
            #pragma unroll
            for (int mf = 0; mf < 4; mf++)
                ldsm4(af[mf], ab + (uint32_t)(mf*16*KPG*4) + kko);
            uint32_t bf0[4], bf1[4];
            ldsm4(bf0, bb + kko);
            ldsm4(bf1, bb + (uint32_t)(16*KPG*4) + kko);
            #pragma unroll
            for (int mf = 0; mf < 4; mf++) {
                mma8(acc[mf][0], af[mf], &bf0[0]);
                mma8(acc[mf][1], af[mf], &bf0[2]);
                mma8(acc[mf][2], af[mf], &bf1[0]);
                mma8(acc[mf][3], af[mf], &bf1[2]);
            }
        }
        __syncthreads();    // all warps done reading stage i
        if (i + 2 < nk) issue(i + 2);
    }

    // epilogue
    #pragma unroll
    for (int mf = 0; mf < 4; mf++) {
        #pragma unroll
        for (int rr = 0; rr < 2; rr++) {
            const int m = bm + wm + mf*16 + g + rr*8;
            const int b = m >> 10;
            const int n = m & 1023;
            #pragma unroll
            for (int nf = 0; nf < 4; nf++) {
                const int c = bn + wn + nf*8 + 2*tig;
                const float vx = acc[mf][nf][rr*2 + 0];
                const float vy = acc[mf][nf][rr*2 + 1];
                if (MODE == 1) {
                    float2 v2; v2.x = vx; v2.y = vy;
                    *(float2*)&Y[(size_t)m * C_ + c] = v2;
                } else {
                    const int s = c / C_;
                    const int w = c - s * C_;
                    const int h = w >> 6;
                    const int d = w & 63;
                    if (s == 0) {
                        float2 v2; v2.x = vx; v2.y = vy;
                        *(float2*)&g_q[((b*H_ + h)*N_ + n)*D_ + d] = v2;
                    } else if (s == 1) {
                        float2 v2; v2.x = vx; v2.y = vy;
                        *(float2*)&g_k[((b*H_ + h)*N_ + n)*D_ + d] = v2;
                    } else {
                        uint32_t* vt = g_vt + ((size_t)(b*H_ + h)*D_ + d)*N_ + n;
                        vt[0]  = f2tf(vx);
                        vt[N_] = f2tf(vy);   // d+1
                    }
                }
            }
        }
    }
}

// ---------------------------------------------------------------------------
// Per-head LayerNorm over D=64. q scale = SCALE * log2(e) (softmax uses ex2).
// Reads fp32, WRITES TF32 BITS.
// ---------------------------------------------------------------------------
__global__ __launch_bounds__(256)
void ln_kernel()
{
    const int warp = (blockIdx.x * blockDim.x + threadIdx.x) >> 5;
    const int lane = threadIdx.x & 31;
    const int nrows = BH_ * N_;
    if (warp >= 2 * nrows) return;

    float* buf  = (warp < nrows) ? g_q : g_k;
    const float scale = (warp < nrows) ? 0.125f * 1.4426950408889634f : 1.0f;
    const int row = (warp < nrows) ? warp : warp - nrows;

    float2 x = *(float2*)&buf[(size_t)row*64 + lane*2];
    float sum = x.x + x.y;
    #pragma unroll
    for (int o = 16; o > 0; o >>= 1) sum += __shfl_xor_sync(0xffffffffu, sum, o);
    const float mean = sum * (1.0f/64.0f);
    const float dx = x.x - mean, dy = x.y - mean;
    float vs = dx*dx + dy*dy;
    #pragma unroll
    for (int o = 16; o > 0; o >>= 1) vs += __shfl_xor_sync(0xffffffffu, vs, o);
    const float inv = rsqrtf(vs * (1.0f/64.0f) + 1e-5f) * scale;
    *(uint2*)&((uint32_t*)buf)[(size_t)row*64 + lane*2] =
        make_uint2(f2tf(dx * inv), f2tf(dy * inv));
}

// ---------------------------------------------------------------------------
// Flash attention v5: 256 threads, 128 q rows/block, cp.async double-buffered
// K/V^T tiles, Q frags hoisted, softmax in log2-space (bare ex2.approx).
// Smem: Ps[128][FPT] (Q staging then P bits) | K0 | V0 | K1 | V1 ([64][FPT]).
// ---------------------------------------------------------------------------
#define FPT 68
#define FTILE_W (64*FPT)
#define PS_W (128*FPT)

__global__ __launch_bounds__(256, 2)
void flash_tf32()
{
    extern __shared__ uint32_t fsm[];
    uint32_t* Ps = fsm;

    const int bh    = blockIdx.y;
    const int qtile = blockIdx.x;       // 0..7 (128 rows each)
    const int b = bh / H_;
    const int h = bh - b * H_;

    const uint32_t* Qb  = (const uint32_t*)g_q + (size_t)bh * N_ * D_
                        + (size_t)qtile * 128 * D_;
    const uint32_t* Kb  = (const uint32_t*)g_k + (size_t)bh * N_ * D_;
    const uint32_t* Vtb = g_vt + (size_t)bh * D_ * N_;

    const int tid  = threadIdx.x;
    const int warp = tid >> 5, lane = tid & 31;
    const int g    = lane >> 2, tig = lane & 3;
    const int wband = warp * 16;

    const uint32_t smbase = smem_u32(fsm);
    const uint32_t bRowOff = (uint32_t)(((lane & 7) + ((lane >> 4) << 3)) * FPT
                                        + (((lane >> 3) & 1) << 2)) * 4;
    const uint32_t pa_lane = smbase
        + (uint32_t)(((wband + (lane & 15)) * FPT + ((lane >> 4) << 2)) * 4);

    auto issue = [&](int j) {
        const int s = j & 1;
        const uint32_t kbase = smbase + (uint32_t)((PS_W + 2*s*FTILE_W) * 4);
        const uint32_t vbase = kbase + (uint32_t)(FTILE_W * 4);
        #pragma unroll
        for (int q = 0; q < 4; q++) {
            const int i = tid + 256*q;
            const int r = i >> 4, ch = (i & 15) << 2;
            cpasync16(kbase + (uint32_t)((r*FPT + ch) * 4),
                      Kb + (size_t)j*4096 + r*64 + ch);
            cpasync16(vbase + (uint32_t)((r*FPT + ch) * 4),
                      Vtb + (size_t)r*N_ + j*64 + ch);
        }
        CP_COMMIT();
    };

    issue(0);
    #pragma unroll
    for (int q = 0; q < 8; q++) {
        const int i = tid + 256*q;
        const int r = i >> 4, ch = (i & 15) << 2;
        *(uint4*)&Ps[r*FPT + ch] = *(const uint4*)(Qb + r*64 + ch);
    }
    __syncthreads();

    uint32_t qa[8][4];
    #pragma unroll
    for (int kf = 0; kf < 8; kf++)
        ldsm4(qa[kf], pa_lane + kf*32);

    float o[8][4];
    #pragma unroll
    for (int nf = 0; nf < 8; nf++)
        #pragma unroll
        for (int e = 0; e < 4; e++) o[nf][e] = 0.f;
    float m0 = -1e30f, m1 = -1e30f, l0 = 0.f, l1 = 0.f;

    for (int j = 0; j < 16; j++) {
        __syncthreads();
        if (j + 1 < 16) {
            issue(j + 1);
            asm volatile("cp.async.wait_group 1;" ::: "memory");
        } else {
            asm volatile("cp.async.wait_group 0;" ::: "memory");
        }
        __syncthreads();

        const int s = j & 1;
        const uint32_t kb_lane = smbase + (uint32_t)((PS_W + 2*s*FTILE_W) * 4) + bRowOff;
        const uint32_t vb_lane = kb_lane + (uint32_t)(FTILE_W * 4);

        // S = Q @ K^T  (log2-scaled scores)
        float sacc[8][4];
        #pragma unroll
        for (int nf = 0; nf < 8; nf++)
            #pragma unroll
            for (int e = 0; e < 4; e++) sacc[nf][e] = 0.f;

        #pragma unroll
        for (int kf = 0; kf < 8; kf++) {
            uint32_t bfr[4][4];
            #pragma unroll
            for (int nfp = 0; nfp < 4; nfp++)
                ldsm4(bfr[nfp], kb_lane + (uint32_t)((nfp*16*FPT + kf*8) * 4));
            #pragma unroll
            for (int nf = 0; nf < 8; nf++)
                mma8(sacc[nf], qa[kf], &bfr[nf >> 1][(nf & 1) * 2]);
        }

        // online softmax in log2 space
        float mx0 = -1e30f, mx1 = -1e30f;
        #pragma unroll
        for (int nf = 0; nf < 8; nf++) {
            mx0 = fmaxf(mx0, fmaxf(sacc[nf][0], sacc[nf][1]));
            mx1 = fmaxf(mx1, fmaxf(sacc[nf][2], sacc[nf][3]));
        }
        mx0 = fmaxf(mx0, __shfl_xor_sync(0xffffffffu, mx0, 1));
        mx0 = fmaxf(mx0, __shfl_xor_sync(0xffffffffu, mx0, 2));
        mx1 = fmaxf(mx1, __shfl_xor_sync(0xffffffffu, mx1, 1));
        mx1 = fmaxf(mx1, __shfl_xor_sync(0xffffffffu, mx1, 2));

        const float mn0 = fmaxf(m0, mx0);
        const float mn1 = fmaxf(m1, mx1);
        const float corr0 = fexp2(m0 - mn0);
        const float corr1 = fexp2(m1 - mn1);
        m0 = mn0; m1 = mn1;

        float rs0 = 0.f, rs1 = 0.f;
        #pragma unroll
        for (int nf = 0; nf < 8; nf++) {
            const float p0 = fexp2(sacc[nf][0] - mn0);
            const float p1 = fexp2(sacc[nf][1] - mn0);
            const float p2 = fexp2(sacc[nf][2] - mn1);
            const float p3 = fexp2(sacc[nf][3] - mn1);
            rs0 += p0 + p1;
            rs1 += p2 + p3;
            *(uint2*)&Ps[(wband + g    )*FPT + nf*8 + 2*tig] =
                make_uint2(f2tf(p0), f2tf(p1));
            *(uint2*)&Ps[(wband + g + 8)*FPT + nf*8 + 2*tig] =
                make_uint2(f2tf(p2), f2tf(p3));
        }
        rs0 += __shfl_xor_sync(0xffffffffu, rs0, 1);
        rs0 += __shfl_xor_sync(0xffffffffu, rs0, 2);
        rs1 += __shfl_xor_sync(0xffffffffu, rs1, 1);
        rs1 += __shfl_xor_sync(0xffffffffu, rs1, 2);
        l0 = l0 * corr0 + rs0;
        l1 = l1 * corr1 + rs1;

        #pragma unroll
        for (int nf = 0; nf < 8; nf++) {
            o[nf][0] *= corr0; o[nf][1] *= corr0;
            o[nf][2] *= corr1; o[nf][3] *= corr1;
        }
        __syncwarp();

        // O += P @ V
        #pragma unroll
        for (int kf = 0; kf < 8; kf++) {
            uint32_t pa[4];
            ldsm4(pa, pa_lane + kf*32);
            uint32_t bv[4][4];
            #pragma unroll
            for (int nfp = 0; nfp < 4; nfp++)
                ldsm4(bv[nfp], vb_lane + (uint32_t)((nfp*16*FPT + kf*8) * 4));
            #pragma unroll
            for (int nf = 0; nf < 8; nf++)
                mma8(o[nf], pa, &bv[nf >> 1][(nf & 1) * 2]);
        }
        __syncwarp();
    }

    // epilogue: O / l -> g_ao as tf32 bits
    const float inv0 = 1.0f / l0;
    const float inv1 = 1.0f / l1;
    const int n0 = qtile*128 + wband + g;
    const int n1 = n0 + 8;
    #pragma unroll
    for (int nf = 0; nf < 8; nf++) {
        const int d = h*64 + nf*8 + 2*tig;
        *(uint2*)&g_ao[((size_t)b*N_ + n0)*C_ + d] =
            make_uint2(f2tf(o[nf][0]*inv0), f2tf(o[nf][1]*inv0));
        *(uint2*)&g_ao[((size_t)b*N_ + n1)*C_ + d] =
            make_uint2(f2tf(o[nf][2]*inv1), f2tf(o[nf][3]*inv1));
    }
}

// ---------------------------------------------------------------------------
extern "C" void kernel_launch(void* const* d_in, const int* in_sizes, int n_in,
                              void* d_out, int out_size)
{
    const float* x     = (const float*)d_in[0];   // [B,N,C]
    const float* wqkv  = (const float*)d_in[1];   // [3C,C]
    const float* wproj = (const float*)d_in[2];   // [C,C]
    float* out = (float*)d_out;                   // [B,N,C]

    uint32_t* d_gx;  cudaGetSymbolAddress((void**)&d_gx,  gx_tf);
    uint32_t* d_gw1; cudaGetSymbolAddress((void**)&d_gw1, gw1_tf);
    uint32_t* d_gw2; cudaGetSymbolAddress((void**)&d_gw2, gw2_tf);
    uint32_t* d_gao; cudaGetSymbolAddress((void**)&d_gao, g_ao);

    const int gsmem = 4 * STG_W * (int)sizeof(uint32_t);   // 73728

    // 0) pre-convert x, wqkv, wproj to tf32 bits
    {
        const int blocks = (NTOTV + 255) / 256;
        cvt_kernel<<<blocks, 256>>>((const float4*)x, (const float4*)wqkv,
                                    (const float4*)wproj);
    }

    // 1) QKV GEMM -> q/k fp32, v transposed tf32 bits (g_vt)
    {
        cudaFuncSetAttribute(gemm_tf32<0>,
                             cudaFuncAttributeMaxDynamicSharedMemorySize, gsmem);
        dim3 grid(3*C_/128, (B_*N_)/128);   // (18, 64)
        gemm_tf32<0><<<grid, 256, gsmem>>>(d_gx, d_gw1, nullptr);
    }

    // 2) LayerNorm on q (*SCALE*log2e) and k -> tf32 bits in place
    {
        const int warps = 2 * BH_ * N_;
        const int blocks = (warps * 32 + 255) / 256;
        ln_kernel<<<blocks, 256>>>();
    }

    // 3) Flash attention -> g_ao (tf32 bits)
    {
        const int fsmem = (PS_W + 4*FTILE_W) * (int)sizeof(uint32_t);   // 104448
        cudaFuncSetAttribute(flash_tf32,
                             cudaFuncAttributeMaxDynamicSharedMemorySize, fsmem);
        dim3 grid(N_/128, BH_);   // (8, 96)
        flash_tf32<<<grid, 256, fsmem>>>();
    }

    // 4) Output projection (A = g_ao tf32 bits)
    {
        cudaFuncSetAttribute(gemm_tf32<1>,
                             cudaFuncAttributeMaxDynamicSharedMemorySize, gsmem);
        dim3 grid(C_/128, (B_*N_)/128);     // (6, 64)
        gemm_tf32<1><<<grid, 256, gsmem>>>(d_gao, d_gw2, out);
    }
}

// round 16
// speedup vs baseline: 1.0292x; 1.0292x over previous
#include <cuda_runtime.h>
#include <math.h>
#include <stdint.h>

#define B_ 8
#define N_ 1024
#define C_ 768
#define H_ 12
#define D_ 64
#define BH_ (B_*H_)

// Scratch (device globals — no allocation allowed)
__device__ float    g_q [BH_*N_*D_];    // fp32 from GEMM; LN rewrites tf32 bits
__device__ float    g_k [BH_*N_*D_];    // fp32 from GEMM; LN rewrites tf32 bits
__device__ uint32_t g_vt[BH_*D_*N_];    // V^T tf32 bits: [bh][d][n]
__device__ uint32_t g_ao[B_*N_*C_];     // attention output, tf32 bits, [B,N,C]
__device__ uint32_t gx_tf [B_*N_*C_];   // x pre-converted to tf32 bits
__device__ uint32_t gw1_tf[3*C_*C_];    // wqkv pre-converted
__device__ uint32_t gw2_tf[C_*C_];      // wproj pre-converted

// ---------------------------------------------------------------------------
// helpers
// ---------------------------------------------------------------------------
__device__ __forceinline__ uint32_t f2tf(float f) {
    uint32_t u;
    asm("cvt.rna.tf32.f32 %0, %1;" : "=r"(u) : "f"(f));
    return u;
}

__device__ __forceinline__ float fexp2(float x) {
    float y;
    asm("ex2.approx.f32 %0, %1;" : "=f"(y) : "f"(x));
    return y;
}

__device__ __forceinline__ void mma8(float* c, const uint32_t* a, const uint32_t* b) {
    asm volatile(
        "mma.sync.aligned.m16n8k8.row.col.f32.tf32.tf32.f32 "
        "{%0,%1,%2,%3},{%4,%5,%6,%7},{%8,%9},{%0,%1,%2,%3};"
        : "+f"(c[0]), "+f"(c[1]), "+f"(c[2]), "+f"(c[3])
        : "r"(a[0]), "r"(a[1]), "r"(a[2]), "r"(a[3]), "r"(b[0]), "r"(b[1]));
}

__device__ __forceinline__ uint32_t smem_u32(const void* p) {
    uint32_t a;
    asm("{ .reg .u64 t; cvta.to.shared.u64 t, %1; cvt.u32.u64 %0, t; }"
        : "=r"(a) : "l"(p));
    return a;
}

__device__ __forceinline__ void ldsm4(uint32_t* r, uint32_t addr) {
    asm volatile("ldmatrix.sync.aligned.m8n8.x4.shared.b16 {%0,%1,%2,%3}, [%4];"
        : "=r"(r[0]), "=r"(r[1]), "=r"(r[2]), "=r"(r[3]) : "r"(addr));
}

__device__ __forceinline__ void cpasync16(uint32_t smem_addr, const void* gptr) {
    asm volatile("cp.async.cg.shared.global [%0], [%1], 16;"
        :: "r"(smem_addr), "l"(gptr) : "memory");
}
#define CP_COMMIT() asm volatile("cp.async.commit_group;" ::: "memory")

// ---------------------------------------------------------------------------
// Pre-convert pass: x, wqkv, wproj -> tf32 bit arrays
// ---------------------------------------------------------------------------
#define NXV ((B_*N_*C_)/4)
#define NW1V ((3*C_*C_)/4)
#define NW2V ((C_*C_)/4)
#define NTOTV (NXV + NW1V + NW2V)

__global__ __launch_bounds__(256)
void cvt_kernel(const float4* __restrict__ x, const float4* __restrict__ w1,
                const float4* __restrict__ w2)
{
    const int i = blockIdx.x * blockDim.x + threadIdx.x;
    if (i >= NTOTV) return;
    float4 v; uint4* dst;
    if (i < NXV)            { v = x[i];               dst = (uint4*)gx_tf  + i; }
    else if (i < NXV+NW1V)  { v = w1[i - NXV];        dst = (uint4*)gw1_tf + (i - NXV); }
    else                    { v = w2[i - NXV - NW1V]; dst = (uint4*)gw2_tf + (i - NXV - NW1V); }
    *dst = make_uint4(f2tf(v.x), f2tf(v.y), f2tf(v.z), f2tf(v.w));
}

// ---------------------------------------------------------------------------
// tf32 GEMM on pre-converted inputs (cp.async 3-stage, LDSM fragments).
// MODE 0: q,k scattered fp32; v scattered TRANSPOSED tf32 bits into g_vt.
// MODE 1: row-major fp32 store to Y.
// ---------------------------------------------------------------------------
#define KPG 36
#define STG_W (128*KPG)

template<int MODE>
__global__ __launch_bounds__(256)
void gemm_tf32(const uint32_t* __restrict__ A, const uint32_t* __restrict__ W,
               float* __restrict__ Y)
{
    extern __shared__ uint32_t smem[];
    uint32_t* As = smem;
    uint32_t* Ws = smem + 3*STG_W;

    const int tid  = threadIdx.x;
    const int warp = tid >> 5, lane = tid & 31;
    const int g    = lane >> 2, tig = lane & 3;
    const int wm   = (warp >> 2) * 64;
    const int wn   = (warp & 3)  * 32;
    const int bm   = blockIdx.y * 128;
    const int bn   = blockIdx.x * 128;
    const int K    = C_;
    const int nk   = K / 32;

    const int lrow = tid >> 1;
    const int lhf  = (tid & 1) * 16;
    const uint32_t sA0 = smem_u32(As) + (uint32_t)((lrow*KPG + lhf) * 4);
    const uint32_t sW0 = smem_u32(Ws) + (uint32_t)((lrow*KPG + lhf) * 4);
    const uint32_t* gA = A + (size_t)(bm + lrow) * K + lhf;
    const uint32_t* gW = W + (size_t)(bn + lrow) * K + lhf;

    const uint32_t a_lane = smem_u32(As)
        + (uint32_t)((((wm + (lane & 15)) * KPG + ((lane >> 4) << 2))) * 4);
    const uint32_t b_lane = smem_u32(Ws)
        + (uint32_t)((((wn + (lane & 7) + ((lane >> 4) << 3)) * KPG
                      + (((lane >> 3) & 1) << 2))) * 4);

    float acc[4][4][4];
    #pragma unroll
    for (int i = 0; i < 4; i++)
        #pragma unroll
        for (int j = 0; j < 4; j++)
            #pragma unroll
            for (int e = 0; e < 4; e++) acc[i][j][e] = 0.f;

    auto issue = [&](int s) {
        const uint32_t so = (uint32_t)((s % 3) * STG_W * 4);
        const uint32_t* ga = gA + s*32;
        const uint32_t* gw = gW + s*32;
        #pragma unroll
        for (int q = 0; q < 4; q++) {
            cpasync16(sA0 + so + q*16, ga + q*4);
            cpasync16(sW0 + so + q*16, gw + q*4);
        }
        CP_COMMIT();
    };

    issue(0);
    if (nk > 1) issue(1);

    for (int i = 0; i < nk; i++) {
        if (i + 1 < nk) asm volatile("cp.async.wait_group 1;" ::: "memory");
        else            asm volatile("cp.async.wait_group 0;" ::: "memory");
        __syncthreads();
        if (i + 2 < nk) issue(i + 2);

        const uint32_t ab = a_lane + (uint32_t)((i % 3) * STG_W * 4);
        const uint32_t bb = b_lane + (uint32_t)((i % 3) * STG_W * 4);
        #pragma unroll
        for (int kk = 0; kk < 4; kk++) {
            const uint32_t kko = kk * 32;
            uint32_t af[4][4];
            #pragma unroll
            for (int mf = 0; mf < 4; mf++)
                ldsm4(af[mf], ab + (uint32_t)(mf*16*KPG*4) + kko);
            uint32_t bf0[4], bf1[4];
            ldsm4(bf0, bb + kko);
            ldsm4(bf1, bb + (uint32_t)(16*KPG*4) + kko);
            #pragma unroll
            for (int mf = 0; mf < 4; mf++) {
                mma8(acc[mf][0], af[mf], &bf0[0]);
                mma8(acc[mf][1], af[mf], &bf0[2]);
                mma8(acc[mf][2], af[mf], &bf1[0]);
                mma8(acc[mf][3], af[mf], &bf1[2]);
            }
        }
    }

    // epilogue
    #pragma unroll
    for (int mf = 0; mf < 4; mf++) {
        #pragma unroll
        for (int rr = 0; rr < 2; rr++) {
            const int m = bm + wm + mf*16 + g + rr*8;
            const int b = m >> 10;
            const int n = m & 1023;
            #pragma unroll
            for (int nf = 0; nf < 4; nf++) {
                const int c = bn + wn + nf*8 + 2*tig;
                const float vx = acc[mf][nf][rr*2 + 0];
                const float vy = acc[mf][nf][rr*2 + 1];
                if (MODE == 1) {
                    float2 v2; v2.x = vx; v2.y = vy;
                    *(float2*)&Y[(size_t)m * C_ + c] = v2;
                } else {
                    const int s = c / C_;
                    const int w = c - s * C_;
                    const int h = w >> 6;
                    const int d = w & 63;
                    if (s == 0) {
                        float2 v2; v2.x = vx; v2.y = vy;
                        *(float2*)&g_q[((b*H_ + h)*N_ + n)*D_ + d] = v2;
                    } else if (s == 1) {
                        float2 v2; v2.x = vx; v2.y = vy;
                        *(float2*)&g_k[((b*H_ + h)*N_ + n)*D_ + d] = v2;
                    } else {
                        uint32_t* vt = g_vt + ((size_t)(b*H_ + h)*D_ + d)*N_ + n;
                        vt[0]  = f2tf(vx);
                        vt[N_] = f2tf(vy);   // d+1
                    }
                }
            }
        }
    }
}

// ---------------------------------------------------------------------------
// Per-head LayerNorm over D=64. q scale = SCALE * log2(e) (softmax uses ex2).
// Reads fp32, WRITES TF32 BITS.
// ---------------------------------------------------------------------------
__global__ __launch_bounds__(256)
void ln_kernel()
{
    const int warp = (blockIdx.x * blockDim.x + threadIdx.x) >> 5;
    const int lane = threadIdx.x & 31;
    const int nrows = BH_ * N_;
    if (warp >= 2 * nrows) return;

    float* buf  = (warp < nrows) ? g_q : g_k;
    const float scale = (warp < nrows) ? 0.125f * 1.4426950408889634f : 1.0f;
    const int row = (warp < nrows) ? warp : warp - nrows;

    float2 x = *(float2*)&buf[(size_t)row*64 + lane*2];
    float sum = x.x + x.y;
    #pragma unroll
    for (int o = 16; o > 0; o >>= 1) sum += __shfl_xor_sync(0xffffffffu, sum, o);
    const float mean = sum * (1.0f/64.0f);
    const float dx = x.x - mean, dy = x.y - mean;
    float vs = dx*dx + dy*dy;
    #pragma unroll
    for (int o = 16; o > 0; o >>= 1) vs += __shfl_xor_sync(0xffffffffu, vs, o);
    const float inv = rsqrtf(vs * (1.0f/64.0f) + 1e-5f) * scale;
    *(uint2*)&((uint32_t*)buf)[(size_t)row*64 + lane*2] =
        make_uint2(f2tf(dx * inv), f2tf(dy * inv));
}

// ---------------------------------------------------------------------------
// Flash attention: 256 threads, 128 q rows/block, cp.async double-buffered
// K/V^T tiles, Q frags hoisted, softmax in log2-space (bare ex2.approx).
// Smem: Ps[128][FPT] (Q staging then P bits) | K0 | V0 | K1 | V1 ([64][FPT]).
// ---------------------------------------------------------------------------
#define FPT 68
#define FTILE_W (64*FPT)
#define PS_W (128*FPT)

__global__ __launch_bounds__(256, 2)
void flash_tf32()
{
    extern __shared__ uint32_t fsm[];
    uint32_t* Ps = fsm;

    const int bh    = blockIdx.y;
    const int qtile = blockIdx.x;       // 0..7 (128 rows each)
    const int b = bh / H_;
    const int h = bh - b * H_;

    const uint32_t* Qb  = (const uint32_t*)g_q + (size_t)bh * N_ * D_
                        + (size_t)qtile * 128 * D_;
    const uint32_t* Kb  = (const uint32_t*)g_k + (size_t)bh * N_ * D_;
    const uint32_t* Vtb = g_vt + (size_t)bh * D_ * N_;

    const int tid  = threadIdx.x;
    const int warp = tid >> 5, lane = tid & 31;
    const int g    = lane >> 2, tig = lane & 3;
    const int wband = warp * 16;

    const uint32_t smbase = smem_u32(fsm);
    const uint32_t bRowOff = (uint32_t)(((lane & 7) + ((lane >> 4) << 3)) * FPT
                                        + (((lane >> 3) & 1) << 2)) * 4;
    const uint32_t pa_lane = smbase
        + (uint32_t)(((wband + (lane & 15)) * FPT + ((lane >> 4) << 2)) * 4);

    auto issue = [&](int j) {
        const int s = j & 1;
        const uint32_t kbase = smbase + (uint32_t)((PS_W + 2*s*FTILE_W) * 4);
        const uint32_t vbase = kbase + (uint32_t)(FTILE_W * 4);
        #pragma unroll
        for (int q = 0; q < 4; q++) {
            const int i = tid + 256*q;
            const int r = i >> 4, ch = (i & 15) << 2;
            cpasync16(kbase + (uint32_t)((r*FPT + ch) * 4),
                      Kb + (size_t)j*4096 + r*64 + ch);
            cpasync16(vbase + (uint32_t)((r*FPT + ch) * 4),
                      Vtb + (size_t)r*N_ + j*64 + ch);
        }
        CP_COMMIT();
    };

    issue(0);
    #pragma unroll
    for (int q = 0; q < 8; q++) {
        const int i = tid + 256*q;
        const int r = i >> 4, ch = (i & 15) << 2;
        *(uint4*)&Ps[r*FPT + ch] = *(const uint4*)(Qb + r*64 + ch);
    }
    __syncthreads();

    uint32_t qa[8][4];
    #pragma unroll
    for (int kf = 0; kf < 8; kf++)
        ldsm4(qa[kf], pa_lane + kf*32);

    float o[8][4];
    #pragma unroll
    for (int nf = 0; nf < 8; nf++)
        #pragma unroll
        for (int e = 0; e < 4; e++) o[nf][e] = 0.f;
    float m0 = -1e30f, m1 = -1e30f, l0 = 0.f, l1 = 0.f;

    for (int j = 0; j < 16; j++) {
        __syncthreads();
        if (j + 1 < 16) {
            issue(j + 1);
            asm volatile("cp.async.wait_group 1;" ::: "memory");
        } else {
            asm volatile("cp.async.wait_group 0;" ::: "memory");
        }
        __syncthreads();

        const int s = j & 1;
        const uint32_t kb_lane = smbase + (uint32_t)((PS_W + 2*s*FTILE_W) * 4) + bRowOff;
        const uint32_t vb_lane = kb_lane + (uint32_t)(FTILE_W * 4);

        // S = Q @ K^T  (log2-scaled scores)
        float sacc[8][4];
        #pragma unroll
        for (int nf = 0; nf < 8; nf++)
            #pragma unroll
            for (int e = 0; e < 4; e++) sacc[nf][e] = 0.f;

        #pragma unroll
        for (int kf = 0; kf < 8; kf++) {
            uint32_t bfr[4][4];
            #pragma unroll
            for (int nfp = 0; nfp < 4; nfp++)
                ldsm4(bfr[nfp], kb_lane + (uint32_t)((nfp*16*FPT + kf*8) * 4));
            #pragma unroll
            for (int nf = 0; nf < 8; nf++)
                mma8(sacc[nf], qa[kf], &bfr[nf >> 1][(nf & 1) * 2]);
        }

        // online softmax in log2 space
        float mx0 = -1e30f, mx1 = -1e30f;
        #pragma unroll
        for (int nf = 0; nf < 8; nf++) {
            mx0 = fmaxf(mx0, fmaxf(sacc[nf][0], sacc[nf][1]));
            mx1 = fmaxf(mx1, fmaxf(sacc[nf][2], sacc[nf][3]));
        }
        mx0 = fmaxf(mx0, __shfl_xor_sync(0xffffffffu, mx0, 1));
        mx0 = fmaxf(mx0, __shfl_xor_sync(0xffffffffu, mx0, 2));
        mx1 = fmaxf(mx1, __shfl_xor_sync(0xffffffffu, mx1, 1));
        mx1 = fmaxf(mx1, __shfl_xor_sync(0xffffffffu, mx1, 2));

        const float mn0 = fmaxf(m0, mx0);
        const float mn1 = fmaxf(m1, mx1);
        const float corr0 = fexp2(m0 - mn0);
        const float corr1 = fexp2(m1 - mn1);
        m0 = mn0; m1 = mn1;

        float rs0 = 0.f, rs1 = 0.f;
        #pragma unroll
        for (int nf = 0; nf < 8; nf++) {
            const float p0 = fexp2(sacc[nf][0] - mn0);
            const float p1 = fexp2(sacc[nf][1] - mn0);
            const float p2 = fexp2(sacc[nf][2] - mn1);
            const float p3 = fexp2(sacc[nf][3] - mn1);
            rs0 += p0 + p1;
            rs1 += p2 + p3;
            *(uint2*)&Ps[(wband + g    )*FPT + nf*8 + 2*tig] =
                make_uint2(f2tf(p0), f2tf(p1));
            *(uint2*)&Ps[(wband + g + 8)*FPT + nf*8 + 2*tig] =
                make_uint2(f2tf(p2), f2tf(p3));
        }
        rs0 += __shfl_xor_sync(0xffffffffu, rs0, 1);
        rs0 += __shfl_xor_sync(0xffffffffu, rs0, 2);
        rs1 += __shfl_xor_sync(0xffffffffu, rs1, 1);
        rs1 += __shfl_xor_sync(0xffffffffu, rs1, 2);
        l0 = l0 * corr0 + rs0;
        l1 = l1 * corr1 + rs1;

        #pragma unroll
        for (int nf = 0; nf < 8; nf++) {
            o[nf][0] *= corr0; o[nf][1] *= corr0;
            o[nf][2] *= corr1; o[nf][3] *= corr1;
        }
        __syncwarp();

        // O += P @ V
        #pragma unroll
        for (int kf = 0; kf < 8; kf++) {
            uint32_t pa[4];
            ldsm4(pa, pa_lane + kf*32);
            uint32_t bv[4][4];
            #pragma unroll
            for (int nfp = 0; nfp < 4; nfp++)
                ldsm4(bv[nfp], vb_lane + (uint32_t)((nfp*16*FPT + kf*8) * 4));
            #pragma unroll
            for (int nf = 0; nf < 8; nf++)
                mma8(o[nf], pa, &bv[nf >> 1][(nf & 1) * 2]);
        }
        __syncwarp();
    }

    // epilogue: O / l -> g_ao as tf32 bits
    const float inv0 = 1.0f / l0;
    const float inv1 = 1.0f / l1;
    const int n0 = qtile*128 + wband + g;
    const int n1 = n0 + 8;
    #pragma unroll
    for (int nf = 0; nf < 8; nf++) {
        const int d = h*64 + nf*8 + 2*tig;
        *(uint2*)&g_ao[((size_t)b*N_ + n0)*C_ + d] =
            make_uint2(f2tf(o[nf][0]*inv0), f2tf(o[nf][1]*inv0));
        *(uint2*)&g_ao[((size_t)b*N_ + n1)*C_ + d] =
            make_uint2(f2tf(o[nf][2]*inv1), f2tf(o[nf][3]*inv1));
    }
}

// ---------------------------------------------------------------------------
extern "C" void kernel_launch(void* const* d_in, const int* in_sizes, int n_in,
                              void* d_out, int out_size)
{
    const float* x     = (const float*)d_in[0];   // [B,N,C]
    const float* wqkv  = (const float*)d_in[1];   // [3C,C]
    const float* wproj = (const float*)d_in[2];   // [C,C]
    float* out = (float*)d_out;                   // [B,N,C]

    uint32_t* d_gx;  cudaGetSymbolAddress((void**)&d_gx,  gx_tf);
    uint32_t* d_gw1; cudaGetSymbolAddress((void**)&d_gw1, gw1_tf);
    uint32_t* d_gw2; cudaGetSymbolAddress((void**)&d_gw2, gw2_tf);
    uint32_t* d_gao; cudaGetSymbolAddress((void**)&d_gao, g_ao);

    const int gsmem = 6 * STG_W * (int)sizeof(uint32_t);   // 110592

    // 0) pre-convert x, wqkv, wproj to tf32 bits
    {
        const int blocks = (NTOTV + 255) / 256;
        cvt_kernel<<<blocks, 256>>>((const float4*)x, (const float4*)wqkv,
                                    (const float4*)wproj);
    }

    // 1) QKV GEMM -> q/k fp32, v transposed tf32 bits (g_vt)
    {
        cudaFuncSetAttribute(gemm_tf32<0>,
                             cudaFuncAttributeMaxDynamicSharedMemorySize, gsmem);
        dim3 grid(3*C_/128, (B_*N_)/128);   // (18, 64)
        gemm_tf32<0><<<grid, 256, gsmem>>>(d_gx, d_gw1, nullptr);
    }

    // 2) LayerNorm on q (*SCALE*log2e) and k -> tf32 bits in place
    {
        const int warps = 2 * BH_ * N_;
        const int blocks = (warps * 32 + 255) / 256;
        ln_kernel<<<blocks, 256>>>();
    }

    // 3) Flash attention -> g_ao (tf32 bits)
    {
        const int fsmem = (PS_W + 4*FTILE_W) * (int)sizeof(uint32_t);   // 104448
        cudaFuncSetAttribute(flash_tf32,
                             cudaFuncAttributeMaxDynamicSharedMemorySize, fsmem);
        dim3 grid(N_/128, BH_);   // (8, 96)
        flash_tf32<<<grid, 256, fsmem>>>();
    }

    // 4) Output projection (A = g_ao tf32 bits)
    {
        cudaFuncSetAttribute(gemm_tf32<1>,
                             cudaFuncAttributeMaxDynamicSharedMemorySize, gsmem);
        dim3 grid(C_/128, (B_*N_)/128);     // (6, 64)
        gemm_tf32<1><<<grid, 256, gsmem>>>(d_gao, d_gw2, out);
    }
}

// round 17
// speedup vs baseline: 1.9034x; 1.8494x over previous
#include <cuda_runtime.h>
#include <cuda_fp16.h>
#include <math.h>
#include <stdint.h>

#define B_ 8
#define N_ 1024
#define C_ 768
#define H_ 12
#define D_ 64
#define BH_ (B_*H_)

// Scratch (device globals — no allocation allowed)
__device__ float  g_q [BH_*N_*D_];   // fp32 q from GEMM (pre-LN)
__device__ float  g_k [BH_*N_*D_];   // fp32 k from GEMM (pre-LN)
__device__ __half g_qh[BH_*N_*D_];   // LN'd q, fp16 (scale folded w/ log2e)
__device__ __half g_kh[BH_*N_*D_];   // LN'd k, fp16
__device__ __half g_vt[BH_*D_*N_];   // V^T fp16: [bh][d][n]
__device__ __half g_ao[B_*N_*C_];    // attention output fp16, [B,N,C]
__device__ __half gx_h [B_*N_*C_];   // x   -> fp16
__device__ __half gw1_h[3*C_*C_];    // wqkv-> fp16
__device__ __half gw2_h[C_*C_];      // wproj->fp16

// ---------------------------------------------------------------------------
// helpers
// ---------------------------------------------------------------------------
__device__ __forceinline__ float fexp2(float x) {
    float y;
    asm("ex2.approx.f32 %0, %1;" : "=f"(y) : "f"(x));
    return y;
}

__device__ __forceinline__ uint32_t h2u(float a, float b) {
    __half2 h = __floats2half2_rn(a, b);
    return *(uint32_t*)&h;
}

// fp16 mma: D(16x8,f32) += A(16x16,f16) * B(16x8,f16)
__device__ __forceinline__ void mma16(float* c, const uint32_t* a, const uint32_t* b) {
    asm volatile(
        "mma.sync.aligned.m16n8k16.row.col.f32.f16.f16.f32 "
        "{%0,%1,%2,%3},{%4,%5,%6,%7},{%8,%9},{%0,%1,%2,%3};"
        : "+f"(c[0]), "+f"(c[1]), "+f"(c[2]), "+f"(c[3])
        : "r"(a[0]), "r"(a[1]), "r"(a[2]), "r"(a[3]), "r"(b[0]), "r"(b[1]));
}

__device__ __forceinline__ uint32_t smem_u32(const void* p) {
    uint32_t a;
    asm("{ .reg .u64 t; cvta.to.shared.u64 t, %1; cvt.u32.u64 %0, t; }"
        : "=r"(a) : "l"(p));
    return a;
}

__device__ __forceinline__ void ldsm4(uint32_t* r, uint32_t addr) {
    asm volatile("ldmatrix.sync.aligned.m8n8.x4.shared.b16 {%0,%1,%2,%3}, [%4];"
        : "=r"(r[0]), "=r"(r[1]), "=r"(r[2]), "=r"(r[3]) : "r"(addr));
}

__device__ __forceinline__ void cpasync16(uint32_t smem_addr, const void* gptr) {
    asm volatile("cp.async.cg.shared.global [%0], [%1], 16;"
        :: "r"(smem_addr), "l"(gptr) : "memory");
}
#define CP_COMMIT() asm volatile("cp.async.commit_group;" ::: "memory")

// ---------------------------------------------------------------------------
// Pre-convert pass: x, wqkv, wproj -> fp16 arrays (float4 -> 4 halfs)
// ---------------------------------------------------------------------------
#define NXV ((B_*N_*C_)/4)
#define NW1V ((3*C_*C_)/4)
#define NW2V ((C_*C_)/4)
#define NTOTV (NXV + NW1V + NW2V)

__global__ __launch_bounds__(256)
void cvt_kernel(const float4* __restrict__ x, const float4* __restrict__ w1,
                const float4* __restrict__ w2)
{
    const int i = blockIdx.x * blockDim.x + threadIdx.x;
    if (i >= NTOTV) return;
    float4 v; uint2* dst;
    if (i < NXV)            { v = x[i];               dst = (uint2*)gx_h  + i; }
    else if (i < NXV+NW1V)  { v = w1[i - NXV];        dst = (uint2*)gw1_h + (i - NXV); }
    else                    { v = w2[i - NXV - NW1V]; dst = (uint2*)gw2_h + (i - NXV - NW1V); }
    *dst = make_uint2(h2u(v.x, v.y), h2u(v.z, v.w));
}

// ---------------------------------------------------------------------------
// fp16 GEMM: Y[m,c] = sum_k A[m,k]*W[c,k]
// BM=BN=128, BK=32 halfs, 256 threads = 8 warps (2x4), warp 64x32.
// 3-stage cp.async pipeline, m16n8k16 mma, smem pitch 40 halfs (80B).
// MODE 0: q,k -> fp32 g_q/g_k; v -> transposed fp16 g_vt.
// MODE 1: row-major fp32 store to Y.
// ---------------------------------------------------------------------------
#define KPH 40
#define STG_H (128*KPH)    // halfs per matrix per stage (5120)

template<int MODE>
__global__ __launch_bounds__(256)
void gemm_fp16(const __half* __restrict__ A, const __half* __restrict__ W,
               float* __restrict__ Y)
{
    extern __shared__ __half smh[];
    __half* As = smh;                 // 3*STG_H
    __half* Ws = smh + 3*STG_H;       // 3*STG_H

    const int tid  = threadIdx.x;
    const int warp = tid >> 5, lane = tid & 31;
    const int g    = lane >> 2, tig = lane & 3;
    const int wm   = (warp >> 2) * 64;
    const int wn   = (warp & 3)  * 32;
    const int bm   = blockIdx.y * 128;
    const int bn   = blockIdx.x * 128;
    const int K    = C_;
    const int nk   = K / 32;          // 24

    // loader: row = tid>>1, part = (tid&1)*16 halfs (32B each)
    const int lrow = tid >> 1;
    const int lpt  = (tid & 1) * 16;
    const uint32_t sA0 = smem_u32(As) + (uint32_t)((lrow*KPH + lpt) * 2);
    const uint32_t sW0 = smem_u32(Ws) + (uint32_t)((lrow*KPH + lpt) * 2);
    const __half* gA = A + (size_t)(bm + lrow) * K + lpt;
    const __half* gW = W + (size_t)(bn + lrow) * K + lpt;

    // ldmatrix lane addresses (bytes)
    const uint32_t a_lane = smem_u32(As)
        + (uint32_t)(((wm + (lane & 15)) * KPH + ((lane >> 4) << 3)) * 2);
    const uint32_t b_lane = smem_u32(Ws)
        + (uint32_t)(((wn + (lane & 7) + ((lane >> 4) << 3)) * KPH
                     + (((lane >> 3) & 1) << 3)) * 2);

    float acc[4][4][4];
    #pragma unroll
    for (int i = 0; i < 4; i++)
        #pragma unroll
        for (int j = 0; j < 4; j++)
            #pragma unroll
            for (int e = 0; e < 4; e++) acc[i][j][e] = 0.f;

    auto issue = [&](int s) {
        const uint32_t so = (uint32_t)((s % 3) * STG_H * 2);
        const __half* ga = gA + s*32;
        const __half* gw = gW + s*32;
        #pragma unroll
        for (int q = 0; q < 2; q++) {
            cpasync16(sA0 + so + q*16, ga + q*8);
            cpasync16(sW0 + so + q*16, gw + q*8);
        }
        CP_COMMIT();
    };

    issue(0);
    if (nk > 1) issue(1);

    for (int i = 0; i < nk; i++) {
        if (i + 1 < nk) asm volatile("cp.async.wait_group 1;" ::: "memory");
        else            asm volatile("cp.async.wait_group 0;" ::: "memory");
        __syncthreads();
        if (i + 2 < nk) issue(i + 2);

        const uint32_t ab = a_lane + (uint32_t)((i % 3) * STG_H * 2);
        const uint32_t bb = b_lane + (uint32_t)((i % 3) * STG_H * 2);
        #pragma unroll
        for (int kk = 0; kk < 2; kk++) {           // two k16 chunks
            const uint32_t kko = kk * 32;          // 16 halfs
            uint32_t af[4][4];
            #pragma unroll
            for (int mf = 0; mf < 4; mf++)
                ldsm4(af[mf], ab + (uint32_t)(mf*16*KPH*2) + kko);
            uint32_t bf0[4], bf1[4];
            ldsm4(bf0, bb + kko);                          // n-tiles 0,1
            ldsm4(bf1, bb + (uint32_t)(16*KPH*2) + kko);   // n-tiles 2,3
            #pragma unroll
            for (int mf = 0; mf < 4; mf++) {
                mma16(acc[mf][0], af[mf], &bf0[0]);
                mma16(acc[mf][1], af[mf], &bf0[2]);
                mma16(acc[mf][2], af[mf], &bf1[0]);
                mma16(acc[mf][3], af[mf], &bf1[2]);
            }
        }
    }

    // epilogue
    #pragma unroll
    for (int mf = 0; mf < 4; mf++) {
        #pragma unroll
        for (int rr = 0; rr < 2; rr++) {
            const int m = bm + wm + mf*16 + g + rr*8;
            const int b = m >> 10;
            const int n = m & 1023;
            #pragma unroll
            for (int nf = 0; nf < 4; nf++) {
                const int c = bn + wn + nf*8 + 2*tig;
                const float vx = acc[mf][nf][rr*2 + 0];
                const float vy = acc[mf][nf][rr*2 + 1];
                if (MODE == 1) {
                    float2 v2; v2.x = vx; v2.y = vy;
                    *(float2*)&Y[(size_t)m * C_ + c] = v2;
                } else {
                    const int s = c / C_;
                    const int w = c - s * C_;
                    const int h = w >> 6;
                    const int d = w & 63;
                    if (s == 0) {
                        float2 v2; v2.x = vx; v2.y = vy;
                        *(float2*)&g_q[((b*H_ + h)*N_ + n)*D_ + d] = v2;
                    } else if (s == 1) {
                        float2 v2; v2.x = vx; v2.y = vy;
                        *(float2*)&g_k[((b*H_ + h)*N_ + n)*D_ + d] = v2;
                    } else {
                        __half* vt = g_vt + ((size_t)(b*H_ + h)*D_ + d)*N_ + n;
                        vt[0]  = __float2half_rn(vx);
                        vt[N_] = __float2half_rn(vy);   // d+1
                    }
                }
            }
        }
    }
}

// ---------------------------------------------------------------------------
// Per-head LayerNorm over D=64. q scale = SCALE*log2e. fp32 in -> fp16 out.
// ---------------------------------------------------------------------------
__global__ __launch_bounds__(256)
void ln_kernel()
{
    const int warp = (blockIdx.x * blockDim.x + threadIdx.x) >> 5;
    const int lane = threadIdx.x & 31;
    const int nrows = BH_ * N_;
    if (warp >= 2 * nrows) return;

    const float* src = (warp < nrows) ? g_q : g_k;
    __half* dst      = (warp < nrows) ? g_qh : g_kh;
    const float scale = (warp < nrows) ? 0.125f * 1.4426950408889634f : 1.0f;
    const int row = (warp < nrows) ? warp : warp - nrows;

    float2 x = *(float2*)&src[(size_t)row*64 + lane*2];
    float sum = x.x + x.y;
    #pragma unroll
    for (int o = 16; o > 0; o >>= 1) sum += __shfl_xor_sync(0xffffffffu, sum, o);
    const float mean = sum * (1.0f/64.0f);
    const float dx = x.x - mean, dy = x.y - mean;
    float vs = dx*dx + dy*dy;
    #pragma unroll
    for (int o = 16; o > 0; o >>= 1) vs += __shfl_xor_sync(0xffffffffu, vs, o);
    const float inv = rsqrtf(vs * (1.0f/64.0f) + 1e-5f) * scale;
    *(uint32_t*)&dst[(size_t)row*64 + lane*2] = h2u(dx * inv, dy * inv);
}

// ---------------------------------------------------------------------------
// Flash attention fp16: 256 threads, 128 q rows/block, cp.async 2-stage K/V^T,
// Q frags hoisted, log2-space softmax (ex2.approx), m16n8k16 mma.
// Smem (halfs): Ps[128][FPH] (Q staging then P) | K0 | V0 | K1 | V1 [64][FPH].
// ---------------------------------------------------------------------------
#define FPH 72
#define FT_H (64*FPH)      // 4608 halfs per tile
#define PS_H (128*FPH)     // 9216 halfs

__global__ __launch_bounds__(256, 2)
void flash_fp16()
{
    extern __shared__ __half fsh[];
    __half* Ps = fsh;

    const int bh    = blockIdx.y;
    const int qtile = blockIdx.x;       // 0..7 (128 rows each)
    const int b = bh / H_;
    const int h = bh - b * H_;

    const __half* Qb  = g_qh + (size_t)bh * N_ * D_ + (size_t)qtile * 128 * D_;
    const __half* Kb  = g_kh + (size_t)bh * N_ * D_;
    const __half* Vtb = g_vt + (size_t)bh * D_ * N_;

    const int tid  = threadIdx.x;
    const int warp = tid >> 5, lane = tid & 31;
    const int g    = lane >> 2, tig = lane & 3;
    const int wband = warp * 16;

    const uint32_t smbase = smem_u32(fsh);
    // B-operand lane address (K and V^T tiles, pitch FPH halfs)
    const uint32_t bRowOff = (uint32_t)((((lane & 7) + ((lane >> 4) << 3)) * FPH
                                        + (((lane >> 3) & 1) << 3)) * 2);
    // A-operand lane address (Q then P, rows wband.., pitch FPH)
    const uint32_t pa_lane = smbase
        + (uint32_t)(((wband + (lane & 15)) * FPH + ((lane >> 4) << 3)) * 2);

    // stage K + V^T tile j into stage s=j&1 (64 rows x 128B, 32B/thread)
    auto issue = [&](int j) {
        const int s = j & 1;
        const uint32_t kbase = smbase + (uint32_t)((PS_H + 2*s*FT_H) * 2);
        const uint32_t vbase = kbase + (uint32_t)(FT_H * 2);
        const int r  = tid >> 2;
        const int ch = (tid & 3) * 16;   // halfs
        cpasync16(kbase + (uint32_t)((r*FPH + ch) * 2),     Kb + (size_t)j*4096 + r*64 + ch);
        cpasync16(kbase + (uint32_t)((r*FPH + ch + 8) * 2), Kb + (size_t)j*4096 + r*64 + ch + 8);
        cpasync16(vbase + (uint32_t)((r*FPH + ch) * 2),     Vtb + (size_t)r*N_ + j*64 + ch);
        cpasync16(vbase + (uint32_t)((r*FPH + ch + 8) * 2), Vtb + (size_t)r*N_ + j*64 + ch + 8);
        CP_COMMIT();
    };

    issue(0);
    // stage Q (128 rows x 128B), plain copies
    #pragma unroll
    for (int q = 0; q < 2; q++) {
        const int i = tid + 256*q;
        const int r = i >> 2, ch = (i & 3) * 16;
        *(uint4*)&Ps[r*FPH + ch]     = *(const uint4*)(Qb + r*64 + ch);
        *(uint4*)&Ps[r*FPH + ch + 8] = *(const uint4*)(Qb + r*64 + ch + 8);
    }
    __syncthreads();

    // hoist Q frags: 4 k16 chunks
    uint32_t qa[4][4];
    #pragma unroll
    for (int kk = 0; kk < 4; kk++)
        ldsm4(qa[kk], pa_lane + kk*32);

    float o[8][4];
    #pragma unroll
    for (int nf = 0; nf < 8; nf++)
        #pragma unroll
        for (int e = 0; e < 4; e++) o[nf][e] = 0.f;
    float m0 = -1e30f, m1 = -1e30f, l0 = 0.f, l1 = 0.f;

    for (int j = 0; j < 16; j++) {
        __syncthreads();
        if (j + 1 < 16) {
            issue(j + 1);
            asm volatile("cp.async.wait_group 1;" ::: "memory");
        } else {
            asm volatile("cp.async.wait_group 0;" ::: "memory");
        }
        __syncthreads();

        const int s = j & 1;
        const uint32_t kb_lane = smbase + (uint32_t)((PS_H + 2*s*FT_H) * 2) + bRowOff;
        const uint32_t vb_lane = kb_lane + (uint32_t)(FT_H * 2);

        // S = Q @ K^T  (16 q-rows x 64 keys, log2-scaled)
        float sacc[8][4];
        #pragma unroll
        for (int nf = 0; nf < 8; nf++)
            #pragma unroll
            for (int e = 0; e < 4; e++) sacc[nf][e] = 0.f;

        #pragma unroll
        for (int kk = 0; kk < 4; kk++) {
            uint32_t bfr[4][4];
            #pragma unroll
            for (int np = 0; np < 4; np++)
                ldsm4(bfr[np], kb_lane + (uint32_t)(np*16*FPH*2) + kk*32);
            #pragma unroll
            for (int nf = 0; nf < 8; nf++)
                mma16(sacc[nf], qa[kk], &bfr[nf >> 1][(nf & 1) * 2]);
        }

        // online softmax in log2 space
        float mx0 = -1e30f, mx1 = -1e30f;
        #pragma unroll
        for (int nf = 0; nf < 8; nf++) {
            mx0 = fmaxf(mx0, fmaxf(sacc[nf][0], sacc[nf][1]));
            mx1 = fmaxf(mx1, fmaxf(sacc[nf][2], sacc[nf][3]));
        }
        mx0 = fmaxf(mx0, __shfl_xor_sync(0xffffffffu, mx0, 1));
        mx0 = fmaxf(mx0, __shfl_xor_sync(0xffffffffu, mx0, 2));
        mx1 = fmaxf(mx1, __shfl_xor_sync(0xffffffffu, mx1, 1));
        mx1 = fmaxf(mx1, __shfl_xor_sync(0xffffffffu, mx1, 2));

        const float mn0 = fmaxf(m0, mx0);
        const float mn1 = fmaxf(m1, mx1);
        const float corr0 = fexp2(m0 - mn0);
        const float corr1 = fexp2(m1 - mn1);
        m0 = mn0; m1 = mn1;

        float rs0 = 0.f, rs1 = 0.f;
        #pragma unroll
        for (int nf = 0; nf < 8; nf++) {
            const float p0 = fexp2(sacc[nf][0] - mn0);
            const float p1 = fexp2(sacc[nf][1] - mn0);
            const float p2 = fexp2(sacc[nf][2] - mn1);
            const float p3 = fexp2(sacc[nf][3] - mn1);
            rs0 += p0 + p1;
            rs1 += p2 + p3;
            *(uint32_t*)&Ps[(wband + g    )*FPH + nf*8 + 2*tig] = h2u(p0, p1);
            *(uint32_t*)&Ps[(wband + g + 8)*FPH + nf*8 + 2*tig] = h2u(p2, p3);
        }
        rs0 += __shfl_xor_sync(0xffffffffu, rs0, 1);
        rs0 += __shfl_xor_sync(0xffffffffu, rs0, 2);
        rs1 += __shfl_xor_sync(0xffffffffu, rs1, 1);
        rs1 += __shfl_xor_sync(0xffffffffu, rs1, 2);
        l0 = l0 * corr0 + rs0;
        l1 = l1 * corr1 + rs1;

        #pragma unroll
        for (int nf = 0; nf < 8; nf++) {
            o[nf][0] *= corr0; o[nf][1] *= corr0;
            o[nf][2] *= corr1; o[nf][3] *= corr1;
        }
        __syncwarp();

        // O += P @ V  (k = 64 keys in 4 k16 chunks; n = 64 d-cols)
        #pragma unroll
        for (int kk = 0; kk < 4; kk++) {
            uint32_t pa[4];
            ldsm4(pa, pa_lane + kk*32);
            uint32_t bv[4][4];
            #pragma unroll
            for (int np = 0; np < 4; np++)
                ldsm4(bv[np], vb_lane + (uint32_t)(np*16*FPH*2) + kk*32);
            #pragma unroll
            for (int nf = 0; nf < 8; nf++)
                mma16(o[nf], pa, &bv[nf >> 1][(nf & 1) * 2]);
        }
        __syncwarp();
    }

    // epilogue: O / l -> g_ao fp16
    const float inv0 = 1.0f / l0;
    const float inv1 = 1.0f / l1;
    const int n0 = qtile*128 + wband + g;
    const int n1 = n0 + 8;
    #pragma unroll
    for (int nf = 0; nf < 8; nf++) {
        const int d = h*64 + nf*8 + 2*tig;
        *(uint32_t*)&g_ao[((size_t)b*N_ + n0)*C_ + d] = h2u(o[nf][0]*inv0, o[nf][1]*inv0);
        *(uint32_t*)&g_ao[((size_t)b*N_ + n1)*C_ + d] = h2u(o[nf][2]*inv1, o[nf][3]*inv1);
    }
}

// ---------------------------------------------------------------------------
extern "C" void kernel_launch(void* const* d_in, const int* in_sizes, int n_in,
                              void* d_out, int out_size)
{
    const float* x     = (const float*)d_in[0];   // [B,N,C]
    const float* wqkv  = (const float*)d_in[1];   // [3C,C]
    const float* wproj = (const float*)d_in[2];   // [C,C]
    float* out = (float*)d_out;                   // [B,N,C]

    __half* d_gx;  cudaGetSymbolAddress((void**)&d_gx,  gx_h);
    __half* d_gw1; cudaGetSymbolAddress((void**)&d_gw1, gw1_h);
    __half* d_gw2; cudaGetSymbolAddress((void**)&d_gw2, gw2_h);
    __half* d_gao; cudaGetSymbolAddress((void**)&d_gao, g_ao);

    const int gsmem = 6 * STG_H * (int)sizeof(__half);   // 61440

    // 0) pre-convert x, wqkv, wproj to fp16
    {
        const int blocks = (NTOTV + 255) / 256;
        cvt_kernel<<<blocks, 256>>>((const float4*)x, (const float4*)wqkv,
                                    (const float4*)wproj);
    }

    // 1) QKV GEMM -> q/k fp32, v transposed fp16 (g_vt)
    {
        cudaFuncSetAttribute(gemm_fp16<0>,
                             cudaFuncAttributeMaxDynamicSharedMemorySize, gsmem);
        dim3 grid(3*C_/128, (B_*N_)/128);   // (18, 64)
        gemm_fp16<0><<<grid, 256, gsmem>>>(d_gx, d_gw1, nullptr);
    }

    // 2) LayerNorm on q (*SCALE*log2e) and k -> fp16 (g_qh/g_kh)
    {
        const int warps = 2 * BH_ * N_;
        const int blocks = (warps * 32 + 255) / 256;
        ln_kernel<<<blocks, 256>>>();
    }

    // 3) Flash attention -> g_ao (fp16)
    {
        const int fsmem = (PS_H + 4*FT_H) * (int)sizeof(__half);   // 55296
        cudaFuncSetAttribute(flash_fp16,
                             cudaFuncAttributeMaxDynamicSharedMemorySize, fsmem);
        dim3 grid(N_/128, BH_);   // (8, 96)
        flash_fp16<<<grid, 256, fsmem>>>();
    }

    // 4) Output projection (A = g_ao fp16)
    {
        cudaFuncSetAttribute(gemm_fp16<1>,
                             cudaFuncAttributeMaxDynamicSharedMemorySize, gsmem);
        dim3 grid(C_/128, (B_*N_)/128);     // (6, 64)
        gemm_fp16<1><<<grid, 256, gsmem>>>(d_gao, d_gw2, out);
    }
}